// round 1
// baseline (speedup 1.0000x reference)
#include <cuda_runtime.h>

// ---------------------------------------------------------------------------
// MultiHeadAttention: b=2, t=2048, emb=512, heads=8, head_dim=512
//   q/k/v = x @ W{q,k,v}.T       (4096 x 512) @ (512 x 4096)
//   S     = q k^T / sqrt(512)    per (b,h), causal
//   P     = softmax(S)           (exact zeros above diagonal)
//   O     = P v
//   y     = O @ Wc.T + bc
// ---------------------------------------------------------------------------

namespace {
constexpr int Bb  = 2;
constexpr int T   = 2048;
constexpr int E   = 512;
constexpr int H   = 8;
constexpr int HE  = H * E;     // 4096
constexpr int BT  = Bb * T;    // 4096
constexpr int NBH = Bb * H;    // 16

constexpr int BM = 128, BN = 128, BK = 16;
constexpr int PADM = BM + 4;   // 132 (16B-aligned rows, reduced bank conflicts)
constexpr int PADN = BN + 4;
}

// Static scratch (allocation-free rule: __device__ globals)
__device__ float g_q[(size_t)BT * HE];
__device__ float g_k[(size_t)BT * HE];
__device__ float g_v[(size_t)BT * HE];
__device__ float g_o[(size_t)BT * HE];
__device__ float g_s[(size_t)NBH * T * T];

// ---------------------------------------------------------------------------
// Shared GEMM mainloop. 256 threads, 128x128 tile, BK=16, 8x8 microtile.
//   NT (BNT=true):  C[m][n] = sum_k A[m][k] * B[n][k]   (B is N x K, k-major)
//   NN (BNT=false): C[m][n] = sum_k A[m][k] * B[k][n]   (B is K x N)
// A points at tile row m0 (col 0). For NT, B points at tile row n0 (col 0).
// For NN, B points at column n0 (row 0).
// ---------------------------------------------------------------------------
template <bool BNT>
__device__ __forceinline__ void gemm_mainloop(
    const float* __restrict__ A, int lda,
    const float* __restrict__ Bp, int ldb,
    int kIters, float acc[8][8])
{
    __shared__ float As[BK][PADM];
    __shared__ float Bs[BK][PADN];

    const int tid = threadIdx.x;
    const int tr  = (tid >> 4) << 3;   // 0..120 step 8
    const int tc  = (tid & 15) << 3;   // 0..120 step 8

    for (int kt = 0; kt < kIters; ++kt) {
        const int k0 = kt * BK;
#pragma unroll
        for (int it = 0; it < 2; ++it) {
            const int f  = tid + it * 256;     // 0..511
            const int m  = f >> 2;             // 0..127
            const int c4 = (f & 3) << 2;       // 0,4,8,12

            float4 va = *(const float4*)(A + (size_t)m * lda + k0 + c4);
            As[c4 + 0][m] = va.x;
            As[c4 + 1][m] = va.y;
            As[c4 + 2][m] = va.z;
            As[c4 + 3][m] = va.w;

            if (BNT) {
                float4 vb = *(const float4*)(Bp + (size_t)m * ldb + k0 + c4);
                Bs[c4 + 0][m] = vb.x;
                Bs[c4 + 1][m] = vb.y;
                Bs[c4 + 2][m] = vb.z;
                Bs[c4 + 3][m] = vb.w;
            } else {
                const int kk = f >> 5;          // 0..15
                const int c  = (f & 31) << 2;   // 0..124
                float4 vb = *(const float4*)(Bp + (size_t)(k0 + kk) * ldb + c);
                *(float4*)&Bs[kk][c] = vb;
            }
        }
        __syncthreads();

#pragma unroll
        for (int k = 0; k < BK; ++k) {
            float a[8], b[8];
            *(float4*)(a)     = *(const float4*)&As[k][tr];
            *(float4*)(a + 4) = *(const float4*)&As[k][tr + 4];
            *(float4*)(b)     = *(const float4*)&Bs[k][tc];
            *(float4*)(b + 4) = *(const float4*)&Bs[k][tc + 4];
#pragma unroll
            for (int i = 0; i < 8; ++i)
#pragma unroll
                for (int j = 0; j < 8; ++j)
                    acc[i][j] += a[i] * b[j];
        }
        __syncthreads();
    }
}

__device__ __forceinline__ void store_tile(
    float* __restrict__ C, int ldc, const float acc[8][8],
    float scale, const float* __restrict__ bias, int n0)
{
    const int tid = threadIdx.x;
    const int tr  = (tid >> 4) << 3;
    const int tc  = (tid & 15) << 3;
#pragma unroll
    for (int i = 0; i < 8; ++i) {
        float4 v0, v1;
        v0.x = acc[i][0] * scale; v0.y = acc[i][1] * scale;
        v0.z = acc[i][2] * scale; v0.w = acc[i][3] * scale;
        v1.x = acc[i][4] * scale; v1.y = acc[i][5] * scale;
        v1.z = acc[i][6] * scale; v1.w = acc[i][7] * scale;
        if (bias) {
            v0.x += bias[n0 + tc + 0]; v0.y += bias[n0 + tc + 1];
            v0.z += bias[n0 + tc + 2]; v0.w += bias[n0 + tc + 3];
            v1.x += bias[n0 + tc + 4]; v1.y += bias[n0 + tc + 5];
            v1.z += bias[n0 + tc + 6]; v1.w += bias[n0 + tc + 7];
        }
        *(float4*)(C + (size_t)(tr + i) * ldc + tc)     = v0;
        *(float4*)(C + (size_t)(tr + i) * ldc + tc + 4) = v1;
    }
}

// ---------------------------------------------------------------------------
// 1) Projection: out[m][n] = sum_k x[m][k] * W[n][k];  which: 0=q, 1=k, 2=v
// ---------------------------------------------------------------------------
__global__ void __launch_bounds__(256, 2)
k_proj(const float* __restrict__ x, const float* __restrict__ W, int which)
{
    const int m0 = blockIdx.y * BM;
    const int n0 = blockIdx.x * BN;
    float acc[8][8] = {};
    gemm_mainloop<true>(x + (size_t)m0 * E, E, W + (size_t)n0 * E, E, E / BK, acc);
    float* out = (which == 0) ? g_q : (which == 1) ? g_k : g_v;
    store_tile(out + (size_t)m0 * HE + n0, HE, acc, 1.0f, nullptr, 0);
}

// ---------------------------------------------------------------------------
// 2) Scores: S[bh][q][k] = (Q . K) / sqrt(E), skip fully-masked tiles
// ---------------------------------------------------------------------------
__global__ void __launch_bounds__(256, 2)
k_scores()
{
    const int bh = blockIdx.z;
    const int m0 = blockIdx.y * BM;
    const int n0 = blockIdx.x * BN;
    if (n0 > m0) return;  // tile entirely above the diagonal: softmax never reads it
    const int b = bh >> 3, h = bh & 7;
    const float* A  = g_q + (size_t)b * T * HE + (size_t)h * E + (size_t)m0 * HE;
    const float* Bp = g_k + (size_t)b * T * HE + (size_t)h * E + (size_t)n0 * HE;
    float acc[8][8] = {};
    gemm_mainloop<true>(A, HE, Bp, HE, E / BK, acc);
    float* S = g_s + (size_t)bh * T * T + (size_t)m0 * T + n0;
    store_tile(S, T, acc, 0.04419417382415922f /* 1/sqrt(512) */, nullptr, 0);
}

// ---------------------------------------------------------------------------
// 3) Row softmax with causal mask; writes exact zeros for k > q.
//    One block per row (256 threads x 8 elements = 2048).
// ---------------------------------------------------------------------------
__global__ void __launch_bounds__(256)
k_softmax()
{
    const int row = blockIdx.x;        // bh*T + q
    const int qi  = row & (T - 1);
    float* Sp = g_s + (size_t)row * T;
    const int tid = threadIdx.x;

    __shared__ float red[8];

    float v[8];
    float mx = -3.0e38f;
#pragma unroll
    for (int i = 0; i < 8; ++i) {
        const int c = tid + (i << 8);
        v[i] = -3.0e38f;
        if (c <= qi) v[i] = Sp[c];
        mx = fmaxf(mx, v[i]);
    }
#pragma unroll
    for (int o = 16; o; o >>= 1) mx = fmaxf(mx, __shfl_xor_sync(0xffffffffu, mx, o));
    if ((tid & 31) == 0) red[tid >> 5] = mx;
    __syncthreads();
    mx = red[0];
#pragma unroll
    for (int w = 1; w < 8; ++w) mx = fmaxf(mx, red[w]);

    float sum = 0.f;
#pragma unroll
    for (int i = 0; i < 8; ++i) {
        const int c = tid + (i << 8);
        float e = 0.f;
        if (c <= qi) e = __expf(v[i] - mx);
        v[i] = e;
        sum += e;
    }
#pragma unroll
    for (int o = 16; o; o >>= 1) sum += __shfl_xor_sync(0xffffffffu, sum, o);
    __syncthreads();                    // red[] reuse
    if ((tid & 31) == 0) red[tid >> 5] = sum;
    __syncthreads();
    sum = red[0];
#pragma unroll
    for (int w = 1; w < 8; ++w) sum += red[w];

    const float inv = 1.0f / sum;
#pragma unroll
    for (int i = 0; i < 8; ++i) {
        const int c = tid + (i << 8);
        Sp[c] = v[i] * inv;             // masked entries -> exact 0
    }
}

// ---------------------------------------------------------------------------
// 4) O = P @ V (NN GEMM), K-loop truncated at the causal boundary
// ---------------------------------------------------------------------------
__global__ void __launch_bounds__(256, 2)
k_pv()
{
    const int bh = blockIdx.z;
    const int m0 = blockIdx.y * BM;
    const int n0 = blockIdx.x * BN;    // over E=512 -> 4 tiles
    const int b = bh >> 3, h = bh & 7;
    const float* A  = g_s + (size_t)bh * T * T + (size_t)m0 * T;
    const float* Bp = g_v + (size_t)b * T * HE + (size_t)h * E + n0;
    float acc[8][8] = {};
    gemm_mainloop<false>(A, T, Bp, HE, (m0 + BM) / BK, acc);
    float* C = g_o + (size_t)b * T * HE + (size_t)h * E + (size_t)m0 * HE + n0;
    store_tile(C, HE, acc, 1.0f, nullptr, 0);
}

// ---------------------------------------------------------------------------
// 5) y = O @ Wc.T + bc
// ---------------------------------------------------------------------------
__global__ void __launch_bounds__(256, 2)
k_out(const float* __restrict__ Wc, const float* __restrict__ bc,
      float* __restrict__ y)
{
    const int m0 = blockIdx.y * BM;
    const int n0 = blockIdx.x * BN;    // over E=512 -> 4 tiles
    float acc[8][8] = {};
    gemm_mainloop<true>(g_o + (size_t)m0 * HE, HE, Wc + (size_t)n0 * HE, HE,
                        HE / BK, acc);
    store_tile(y + (size_t)m0 * E + n0, E, acc, 1.0f, bc, n0);
}

// ---------------------------------------------------------------------------
extern "C" void kernel_launch(void* const* d_in, const int* in_sizes, int n_in,
                              void* d_out, int out_size)
{
    const float* x  = (const float*)d_in[0];
    const float* Wk = (const float*)d_in[1];
    const float* Wq = (const float*)d_in[2];
    const float* Wv = (const float*)d_in[3];
    const float* Wc = (const float*)d_in[4];
    const float* bc = (const float*)d_in[5];
    float* y = (float*)d_out;

    const dim3 thr(256);
    k_proj<<<dim3(HE / BN, BT / BM), thr>>>(x, Wq, 0);
    k_proj<<<dim3(HE / BN, BT / BM), thr>>>(x, Wk, 1);
    k_proj<<<dim3(HE / BN, BT / BM), thr>>>(x, Wv, 2);
    k_scores<<<dim3(T / BN, T / BM, NBH), thr>>>();
    k_softmax<<<dim3(NBH * T), thr>>>();
    k_pv<<<dim3(E / BN, T / BM, NBH), thr>>>();
    k_out<<<dim3(E / BN, BT / BM), thr>>>(Wc, bc, y);
}